// round 15
// baseline (speedup 1.0000x reference)
#include <cuda_runtime.h>
#include <cuda_fp16.h>
#include <cstdint>
#include <cstddef>

#define AGENTS 8192
#define FDIM   128
#define PDIM   16
#define EDGES  262144
#define CAP    128          // max edges per source row (mean 32; P(>128) ~ e^-81)

// Per-row packed vectors, both fp16 (256 halves = 512B per row).
// g_ph[i]: [ alpha_i * nf_i | (gamma_i/F) * diff_i ]   (src side)
// g_qh[i]: [ nf_i           | diff_i ]                 (dst side, gathered)
__device__ __half g_ph[(size_t)AGENTS * 2 * FDIM];
__device__ __half g_qh[(size_t)AGENTS * 2 * FDIM];
__device__ float  g_beta[AGENTS];

// Slot-array CSR, dst as uint16. Counters zero at load; RESET by fused_kernel.
__device__ int g_act_cnt[AGENTS];
__device__ int g_cost_cnt[AGENTS];
__device__ unsigned short g_act_slot[(size_t)AGENTS * CAP];
__device__ unsigned short g_cost_slot[(size_t)AGENTS * CAP];

// ---------------------------------------------------------------------------
// Kernel 1 (combined): blocks [0,1024) = prep (warp-per-row, 8 rows/block),
//                      blocks [1024,2048) = edge bucketing (1 edge/thread).
// ---------------------------------------------------------------------------
__global__ void __launch_bounds__(256) pre_kernel(
    const float* __restrict__ feature,
    const float* __restrict__ next_feature,
    const float* __restrict__ persona,
    const float* __restrict__ alpha,
    const float* __restrict__ beta,
    const float* __restrict__ gamma,
    const int* __restrict__ act_src,
    const int* __restrict__ act_dst,
    const int* __restrict__ edge_src,
    const int* __restrict__ edge_dst)
{
    const int tid = threadIdx.x;

    if (blockIdx.x >= 1024) {
        const int e = (blockIdx.x - 1024) * 256 + tid;   // exactly covers EDGES
        {
            int s = act_src[e];
            int slot = atomicAdd(&g_act_cnt[s], 1);
            g_act_slot[(size_t)s * CAP + slot] = (unsigned short)act_dst[e];
        }
        {
            int s = edge_src[e];
            int slot = atomicAdd(&g_cost_cnt[s], 1);
            g_cost_slot[(size_t)s * CAP + slot] = (unsigned short)edge_dst[e];
        }
        asm volatile("griddepcontrol.launch_dependents;");
        return;
    }

    // ---- prep: one warp per row ----
    const int lane = tid & 31;
    const int row  = blockIdx.x * 8 + (tid >> 5);

    const float4 f4 = ((const float4*)feature)[row * 32 + lane];
    const float4 n4 = ((const float4*)next_feature)[row * 32 + lane];
    float4 diff;
    diff.x = f4.x - n4.x; diff.y = f4.y - n4.y;
    diff.z = f4.z - n4.z; diff.w = f4.w - n4.w;

    float a = 0.f, b = 0.f, g = 0.f;
    const float4* __restrict__ pr = (const float4*)(persona + row * PDIM);
    const float4* __restrict__ al = (const float4*)alpha;
    const float4* __restrict__ be = (const float4*)beta;
    const float4* __restrict__ ga = (const float4*)gamma;
#pragma unroll
    for (int j = 0; j < 4; j++) {
        const float4 pv = pr[j];
        const float4 av = al[j], bv = be[j], gv = ga[j];
        a = fmaf(pv.x, av.x, fmaf(pv.y, av.y, fmaf(pv.z, av.z, fmaf(pv.w, av.w, a))));
        b = fmaf(pv.x, bv.x, fmaf(pv.y, bv.y, fmaf(pv.z, bv.z, fmaf(pv.w, bv.w, b))));
        g = fmaf(pv.x, gv.x, fmaf(pv.y, gv.y, fmaf(pv.z, gv.z, fmaf(pv.w, gv.w, g))));
    }

    // double L2 normalize (reference normalizes twice)
    float s = fmaf(n4.x, n4.x, fmaf(n4.y, n4.y, fmaf(n4.z, n4.z, n4.w * n4.w)));
#pragma unroll
    for (int o = 16; o > 0; o >>= 1) s += __shfl_xor_sync(0xffffffffu, s, o);
    const float n1 = sqrtf(s);
    float4 nf1;
    nf1.x = n4.x / n1; nf1.y = n4.y / n1; nf1.z = n4.z / n1; nf1.w = n4.w / n1;

    s = fmaf(nf1.x, nf1.x, fmaf(nf1.y, nf1.y, fmaf(nf1.z, nf1.z, nf1.w * nf1.w)));
#pragma unroll
    for (int o = 16; o > 0; o >>= 1) s += __shfl_xor_sync(0xffffffffu, s, o);
    const float n2 = sqrtf(s);
    float4 nf;
    nf.x = nf1.x / n2; nf.y = nf1.y / n2; nf.z = nf1.z / n2; nf.w = nf1.w / n2;

    // q in fp16: [nf | diff]
    __half2* __restrict__ qh2 = (__half2*)(g_qh + (size_t)row * 2 * FDIM);
    qh2[2 * lane]          = __floats2half2_rn(nf.x, nf.y);
    qh2[2 * lane + 1]      = __floats2half2_rn(nf.z, nf.w);
    qh2[64 + 2 * lane]     = __floats2half2_rn(diff.x, diff.y);
    qh2[64 + 2 * lane + 1] = __floats2half2_rn(diff.z, diff.w);

    // p in fp16: [a*nf | (g/F)*diff]
    __half2* __restrict__ ph2 = (__half2*)(g_ph + (size_t)row * 2 * FDIM);
    const float gs = g * (1.0f / (float)FDIM);
    ph2[2 * lane]          = __floats2half2_rn(a * nf.x, a * nf.y);
    ph2[2 * lane + 1]      = __floats2half2_rn(a * nf.z, a * nf.w);
    ph2[64 + 2 * lane]     = __floats2half2_rn(gs * diff.x, gs * diff.y);
    ph2[64 + 2 * lane + 1] = __floats2half2_rn(gs * diff.z, gs * diff.w);
    if (lane == 0) g_beta[row] = b;

    asm volatile("griddepcontrol.launch_dependents;");
}

// ---------------------------------------------------------------------------
// Kernel 2: one block per output row. NO row staging in smem:
//   1. stream 32KB of zeros straight to GMEM (__stcs, evict-first stream)
//   2. compute act-edge dot values into a tiny smem array (overlaps stores)
//   3. __syncthreads, then ~64 global atomicAdds into the L2-hot row
// Lane L owns elements [8L, 8L+8); p and q are each one uint4 (8 halves).
// ---------------------------------------------------------------------------
__device__ __forceinline__ float dot8h(const float2 pf[4], const uint4 qv)
{
    const float2 f0 = __half22float2(*(const __half2*)&qv.x);
    const float2 f1 = __half22float2(((const __half2*)&qv.x)[1]);
    const float2 f2 = __half22float2(*(const __half2*)&qv.z);
    const float2 f3 = __half22float2(((const __half2*)&qv.z)[1]);
    float acc = pf[0].x * f0.x;
    acc = fmaf(pf[0].y, f0.y, acc);
    acc = fmaf(pf[1].x, f1.x, acc);
    acc = fmaf(pf[1].y, f1.y, acc);
    acc = fmaf(pf[2].x, f2.x, acc);
    acc = fmaf(pf[2].y, f2.y, acc);
    acc = fmaf(pf[3].x, f3.x, acc);
    acc = fmaf(pf[3].y, f3.y, acc);
    return acc;
}

__global__ void __launch_bounds__(256) fused_kernel(float* __restrict__ out)
{
    const int r    = blockIdx.x;
    const int tid  = threadIdx.x;
    const int lane = tid & 31;
    const int w    = tid >> 5;   // 0..7

    __shared__ float svals[CAP];     // act-edge values (512B only)

    asm volatile("griddepcontrol.wait;" ::: "memory");

    const int act_cnt  = g_act_cnt[r];
    const int cost_cnt = g_cost_cnt[r];

    // this lane's p slice (issued early; latency hides under the zero stores)
    const uint4 pv = __ldg((const uint4*)(g_ph + (size_t)r * 2 * FDIM) + lane);

    // 1) stream the row of zeros directly to GMEM, evict-first
    float* __restrict__ row = out + (size_t)r * AGENTS;
    float4* __restrict__ row4 = (float4*)row;
    const float4 z = make_float4(0.f, 0.f, 0.f, 0.f);
#pragma unroll
    for (int i = 0; i < 8; i++) __stcs(&row4[tid + 256 * i], z);

    float2 pf[4];
    pf[0] = __half22float2(*(const __half2*)&pv.x);
    pf[1] = __half22float2(((const __half2*)&pv.x)[1]);
    pf[2] = __half22float2(*(const __half2*)&pv.z);
    pf[3] = __half22float2(((const __half2*)&pv.z)[1]);

    // 2) act-edge dot values into smem (gathers overlap the store stream)
    {
        const unsigned short* __restrict__ dsts = g_act_slot + (size_t)r * CAP;
        int i = w;
        for (; i + 24 < act_cnt; i += 32) {
            const int dA = dsts[i];
            const int dB = dsts[i + 8];
            const int dC = dsts[i + 16];
            const int dD = dsts[i + 24];
            const uint4 qa = __ldg((const uint4*)(g_qh + (size_t)dA * 2 * FDIM) + lane);
            const uint4 qb = __ldg((const uint4*)(g_qh + (size_t)dB * 2 * FDIM) + lane);
            const uint4 qc = __ldg((const uint4*)(g_qh + (size_t)dC * 2 * FDIM) + lane);
            const uint4 qd = __ldg((const uint4*)(g_qh + (size_t)dD * 2 * FDIM) + lane);
            float accA = dot8h(pf, qa);
            float accB = dot8h(pf, qb);
            float accC = dot8h(pf, qc);
            float accD = dot8h(pf, qd);
#pragma unroll
            for (int o = 16; o > 0; o >>= 1) {
                accA += __shfl_xor_sync(0xffffffffu, accA, o);
                accB += __shfl_xor_sync(0xffffffffu, accB, o);
                accC += __shfl_xor_sync(0xffffffffu, accC, o);
                accD += __shfl_xor_sync(0xffffffffu, accD, o);
            }
            if (lane == 0) {
                svals[i]      = accA;
                svals[i + 8]  = accB;
                svals[i + 16] = accC;
                svals[i + 24] = accD;
            }
        }
        for (; i < act_cnt; i += 8) {
            const int d = dsts[i];
            const uint4 qv = __ldg((const uint4*)(g_qh + (size_t)d * 2 * FDIM) + lane);
            float acc = dot8h(pf, qv);
#pragma unroll
            for (int o = 16; o > 0; o >>= 1)
                acc += __shfl_xor_sync(0xffffffffu, acc, o);
            if (lane == 0) svals[i] = acc;
        }
    }

    // 3) make zeros + svals visible block-wide, then scatter via atomics
    __syncthreads();

    {
        const unsigned short* __restrict__ dsts = g_act_slot + (size_t)r * CAP;
        for (int i = tid; i < act_cnt; i += 256)
            atomicAdd(&row[dsts[i]], svals[i]);
    }
    {
        const float beta_r = g_beta[r];
        const unsigned short* __restrict__ dsts = g_cost_slot + (size_t)r * CAP;
        for (int i = tid; i < cost_cnt; i += 256)
            atomicAdd(&row[dsts[i]], -beta_r);
    }

    // reset consumed counters for the next launch (register copies in use)
    if (tid == 0) { g_act_cnt[r] = 0; g_cost_cnt[r] = 0; }
}

// ---------------------------------------------------------------------------
extern "C" void kernel_launch(void* const* d_in, const int* in_sizes, int n_in,
                              void* d_out, int out_size)
{
    const float* feature      = (const float*)d_in[0];
    const float* next_feature = (const float*)d_in[1];
    const float* persona_t    = (const float*)d_in[2];
    const float* alpha        = (const float*)d_in[3];
    const float* beta         = (const float*)d_in[4];
    const float* gamma        = (const float*)d_in[5];
    const int*   act_src      = (const int*)d_in[6];
    const int*   act_dst      = (const int*)d_in[7];
    const int*   edge_src     = (const int*)d_in[8];
    const int*   edge_dst     = (const int*)d_in[9];
    float* out = (float*)d_out;

    pre_kernel<<<2048, 256>>>(feature, next_feature, persona_t,
                              alpha, beta, gamma,
                              act_src, act_dst, edge_src, edge_dst);

    // PDL launch of fused; wait gates consumption of pre's outputs.
    cudaLaunchConfig_t cfg = {};
    cfg.gridDim  = dim3(AGENTS);
    cfg.blockDim = dim3(256);
    cfg.dynamicSmemBytes = 0;
    cfg.stream = 0;
    cudaLaunchAttribute attrs[1];
    attrs[0].id = cudaLaunchAttributeProgrammaticStreamSerialization;
    attrs[0].val.programmaticStreamSerializationAllowed = 1;
    cfg.attrs = attrs;
    cfg.numAttrs = 1;
    cudaLaunchKernelEx(&cfg, fused_kernel, out);
}

// round 17
// speedup vs baseline: 1.0942x; 1.0942x over previous
#include <cuda_runtime.h>
#include <cuda_fp16.h>
#include <cstdint>
#include <cstddef>

#define AGENTS 8192
#define FDIM   128
#define PDIM   16
#define EDGES  262144
#define CAP    128          // max edges per source row (mean 32; P(>128) ~ e^-81)

// Per-row packed vectors.
// g_p[i]  (fp32): [ alpha_i * nf_i | (gamma_i/F) * diff_i ]   (src side)
// g_qh[i] (fp16): [ nf_i           | diff_i ]                 (dst side, gathered)
__device__ float  g_p[(size_t)AGENTS * 2 * FDIM];
__device__ __half g_qh[(size_t)AGENTS * 2 * FDIM];
__device__ float  g_beta[AGENTS];

// Slot-array CSR. Counters zero at load; RESET by fused_kernel after use.
__device__ int g_act_cnt[AGENTS];
__device__ int g_cost_cnt[AGENTS];
__device__ int g_act_slot[(size_t)AGENTS * CAP];
__device__ int g_cost_slot[(size_t)AGENTS * CAP];

// ---------------------------------------------------------------------------
// Kernel 1 (combined): blocks [0,1024) = prep (warp-per-row, 8 rows/block),
//                      blocks [1024,2048) = edge bucketing (1 edge/thread).
// Ends with griddepcontrol.launch_dependents for the PDL-launched fused grid.
// ---------------------------------------------------------------------------
__global__ void __launch_bounds__(256) pre_kernel(
    const float* __restrict__ feature,
    const float* __restrict__ next_feature,
    const float* __restrict__ persona,
    const float* __restrict__ alpha,
    const float* __restrict__ beta,
    const float* __restrict__ gamma,
    const int* __restrict__ act_src,
    const int* __restrict__ act_dst,
    const int* __restrict__ edge_src,
    const int* __restrict__ edge_dst)
{
    const int tid = threadIdx.x;

    if (blockIdx.x >= 1024) {
        const int e = (blockIdx.x - 1024) * 256 + tid;   // exactly covers EDGES
        {
            int s = act_src[e];
            int slot = atomicAdd(&g_act_cnt[s], 1);
            g_act_slot[(size_t)s * CAP + slot] = act_dst[e];
        }
        {
            int s = edge_src[e];
            int slot = atomicAdd(&g_cost_cnt[s], 1);
            g_cost_slot[(size_t)s * CAP + slot] = edge_dst[e];
        }
        asm volatile("griddepcontrol.launch_dependents;");
        return;
    }

    // ---- prep: one warp per row ----
    const int lane = tid & 31;
    const int row  = blockIdx.x * 8 + (tid >> 5);

    const float4 f4 = ((const float4*)feature)[row * 32 + lane];
    const float4 n4 = ((const float4*)next_feature)[row * 32 + lane];
    float4 diff;
    diff.x = f4.x - n4.x; diff.y = f4.y - n4.y;
    diff.z = f4.z - n4.z; diff.w = f4.w - n4.w;

    float a = 0.f, b = 0.f, g = 0.f;
    const float4* __restrict__ pr = (const float4*)(persona + row * PDIM);
    const float4* __restrict__ al = (const float4*)alpha;
    const float4* __restrict__ be = (const float4*)beta;
    const float4* __restrict__ ga = (const float4*)gamma;
#pragma unroll
    for (int j = 0; j < 4; j++) {
        const float4 pv = pr[j];
        const float4 av = al[j], bv = be[j], gv = ga[j];
        a = fmaf(pv.x, av.x, fmaf(pv.y, av.y, fmaf(pv.z, av.z, fmaf(pv.w, av.w, a))));
        b = fmaf(pv.x, bv.x, fmaf(pv.y, bv.y, fmaf(pv.z, bv.z, fmaf(pv.w, bv.w, b))));
        g = fmaf(pv.x, gv.x, fmaf(pv.y, gv.y, fmaf(pv.z, gv.z, fmaf(pv.w, gv.w, g))));
    }

    // double L2 normalize (reference normalizes twice)
    float s = fmaf(n4.x, n4.x, fmaf(n4.y, n4.y, fmaf(n4.z, n4.z, n4.w * n4.w)));
#pragma unroll
    for (int o = 16; o > 0; o >>= 1) s += __shfl_xor_sync(0xffffffffu, s, o);
    const float n1 = sqrtf(s);
    float4 nf1;
    nf1.x = n4.x / n1; nf1.y = n4.y / n1; nf1.z = n4.z / n1; nf1.w = n4.w / n1;

    s = fmaf(nf1.x, nf1.x, fmaf(nf1.y, nf1.y, fmaf(nf1.z, nf1.z, nf1.w * nf1.w)));
#pragma unroll
    for (int o = 16; o > 0; o >>= 1) s += __shfl_xor_sync(0xffffffffu, s, o);
    const float n2 = sqrtf(s);
    float4 nf;
    nf.x = nf1.x / n2; nf.y = nf1.y / n2; nf.z = nf1.z / n2; nf.w = nf1.w / n2;

    // q in fp16: [nf | diff]
    __half2* __restrict__ qh2 = (__half2*)(g_qh + (size_t)row * 2 * FDIM);
    qh2[2 * lane]          = __floats2half2_rn(nf.x, nf.y);
    qh2[2 * lane + 1]      = __floats2half2_rn(nf.z, nf.w);
    qh2[64 + 2 * lane]     = __floats2half2_rn(diff.x, diff.y);
    qh2[64 + 2 * lane + 1] = __floats2half2_rn(diff.z, diff.w);

    // p in fp32: [a*nf | (g/F)*diff]
    float4* __restrict__ p4 = (float4*)(g_p + (size_t)row * 2 * FDIM);
    float4 pa, pg;
    pa.x = a * nf.x; pa.y = a * nf.y; pa.z = a * nf.z; pa.w = a * nf.w;
    const float gs = g * (1.0f / (float)FDIM);
    pg.x = gs * diff.x; pg.y = gs * diff.y; pg.z = gs * diff.z; pg.w = gs * diff.w;
    p4[lane]      = pa;
    p4[lane + 32] = pg;
    if (lane == 0) g_beta[row] = b;

    asm volatile("griddepcontrol.launch_dependents;");
}

// ---------------------------------------------------------------------------
// Kernel 2: one block per output row (32KB smem accumulator), PDL-launched.
// smem zero overlaps pre's tail; griddepcontrol.wait gates data reads.
// Output written EXACTLY ONCE via evict-first TMA bulk store (minimal DRAM
// bytes — the binding budget), read-side-only wait so CTAs retire early.
// Dot layout: lane L owns elements [8L, 8L+8) of the 256-dim vectors.
// ---------------------------------------------------------------------------
__device__ __forceinline__ float dot8(const float4 p0, const float4 p1, const uint4 qv)
{
    const __half2 h0 = *(const __half2*)&qv.x;
    const __half2 h1 = ((const __half2*)&qv.x)[1];
    const __half2 h2 = *(const __half2*)&qv.z;
    const __half2 h3 = ((const __half2*)&qv.z)[1];
    const float2 f0 = __half22float2(h0);
    const float2 f1 = __half22float2(h1);
    const float2 f2 = __half22float2(h2);
    const float2 f3 = __half22float2(h3);
    float acc = p0.x * f0.x;
    acc = fmaf(p0.y, f0.y, acc);
    acc = fmaf(p0.z, f1.x, acc);
    acc = fmaf(p0.w, f1.y, acc);
    acc = fmaf(p1.x, f2.x, acc);
    acc = fmaf(p1.y, f2.y, acc);
    acc = fmaf(p1.z, f3.x, acc);
    acc = fmaf(p1.w, f3.y, acc);
    return acc;
}

__global__ void __launch_bounds__(256) fused_kernel(float* __restrict__ out)
{
    const int r    = blockIdx.x;
    const int tid  = threadIdx.x;
    const int lane = tid & 31;
    const int w    = tid >> 5;   // 0..7

    __shared__ float srow[AGENTS];   // 32KB row accumulator

    // zero smem row buffer FIRST — independent of pre's outputs (PDL overlap)
    float4* srow4 = (float4*)srow;
    const float4 z = make_float4(0.f, 0.f, 0.f, 0.f);
#pragma unroll
    for (int i = 0; i < 8; i++) srow4[tid + 256 * i] = z;

    asm volatile("griddepcontrol.wait;" ::: "memory");

    const int act_cnt  = g_act_cnt[r];
    const int cost_cnt = g_cost_cnt[r];
    const float4* __restrict__ pp = (const float4*)(g_p + (size_t)r * 2 * FDIM);
    const float4 p0 = __ldg(&pp[2 * lane]);
    const float4 p1 = __ldg(&pp[2 * lane + 1]);
    __syncthreads();

    // act edges: 8 warps stride the list; 4-edge batches for MLP=4
    {
        const int* __restrict__ dsts = g_act_slot + (size_t)r * CAP;
        int i = w;
        for (; i + 24 < act_cnt; i += 32) {
            const int dA = dsts[i];
            const int dB = dsts[i + 8];
            const int dC = dsts[i + 16];
            const int dD = dsts[i + 24];
            const uint4 qa = __ldg((const uint4*)(g_qh + (size_t)dA * 2 * FDIM) + lane);
            const uint4 qb = __ldg((const uint4*)(g_qh + (size_t)dB * 2 * FDIM) + lane);
            const uint4 qc = __ldg((const uint4*)(g_qh + (size_t)dC * 2 * FDIM) + lane);
            const uint4 qd = __ldg((const uint4*)(g_qh + (size_t)dD * 2 * FDIM) + lane);
            float accA = dot8(p0, p1, qa);
            float accB = dot8(p0, p1, qb);
            float accC = dot8(p0, p1, qc);
            float accD = dot8(p0, p1, qd);
#pragma unroll
            for (int o = 16; o > 0; o >>= 1) {
                accA += __shfl_xor_sync(0xffffffffu, accA, o);
                accB += __shfl_xor_sync(0xffffffffu, accB, o);
                accC += __shfl_xor_sync(0xffffffffu, accC, o);
                accD += __shfl_xor_sync(0xffffffffu, accD, o);
            }
            if (lane == 0) {
                atomicAdd(&srow[dA], accA);
                atomicAdd(&srow[dB], accB);
                atomicAdd(&srow[dC], accC);
                atomicAdd(&srow[dD], accD);
            }
        }
        for (; i < act_cnt; i += 8) {
            const int d = dsts[i];
            const uint4 qv = __ldg((const uint4*)(g_qh + (size_t)d * 2 * FDIM) + lane);
            float acc = dot8(p0, p1, qv);
#pragma unroll
            for (int o = 16; o > 0; o >>= 1)
                acc += __shfl_xor_sync(0xffffffffu, acc, o);
            if (lane == 0) atomicAdd(&srow[d], acc);
        }
    }

    // cost edges
    {
        const float beta_r = g_beta[r];
        const int* __restrict__ dsts = g_cost_slot + (size_t)r * CAP;
        for (int i = tid; i < cost_cnt; i += 256)
            atomicAdd(&srow[dsts[i]], -beta_r);
    }

    __syncthreads();

    // reset consumed counters for the next launch (after all reads)
    if (tid == 0) { g_act_cnt[r] = 0; g_cost_cnt[r] = 0; }

    // single evict-first TMA bulk store of the finished 32KB row.
    // wait only for the smem READ side so the CTA retires while writes drain.
    if (tid == 0) {
        uint32_t saddr;
        asm("{ .reg .u64 t; cvta.to.shared.u64 t, %1; cvt.u32.u64 %0, t; }"
            : "=r"(saddr) : "l"((const void*)srow));
        float* gptr = out + (size_t)r * AGENTS;
        uint64_t policy;
        asm("createpolicy.fractional.L2::evict_first.b64 %0, 1.0;" : "=l"(policy));
        asm volatile("fence.proxy.async.shared::cta;" ::: "memory");
        asm volatile(
            "cp.async.bulk.global.shared::cta.bulk_group.L2::cache_hint "
            "[%0], [%1], %2, %3;"
            :: "l"(gptr), "r"(saddr), "r"((int)(AGENTS * 4)), "l"(policy)
            : "memory");
        asm volatile("cp.async.bulk.commit_group;" ::: "memory");
        asm volatile("cp.async.bulk.wait_group.read 0;" ::: "memory");
    }
}

// ---------------------------------------------------------------------------
extern "C" void kernel_launch(void* const* d_in, const int* in_sizes, int n_in,
                              void* d_out, int out_size)
{
    const float* feature      = (const float*)d_in[0];
    const float* next_feature = (const float*)d_in[1];
    const float* persona_t    = (const float*)d_in[2];
    const float* alpha        = (const float*)d_in[3];
    const float* beta         = (const float*)d_in[4];
    const float* gamma        = (const float*)d_in[5];
    const int*   act_src      = (const int*)d_in[6];
    const int*   act_dst      = (const int*)d_in[7];
    const int*   edge_src     = (const int*)d_in[8];
    const int*   edge_dst     = (const int*)d_in[9];
    float* out = (float*)d_out;

    pre_kernel<<<2048, 256>>>(feature, next_feature, persona_t,
                              alpha, beta, gamma,
                              act_src, act_dst, edge_src, edge_dst);

    // PDL launch of fused: smem zero overlaps pre; wait gates data reads.
    cudaLaunchConfig_t cfg = {};
    cfg.gridDim  = dim3(AGENTS);
    cfg.blockDim = dim3(256);
    cfg.dynamicSmemBytes = 0;
    cfg.stream = 0;
    cudaLaunchAttribute attrs[1];
    attrs[0].id = cudaLaunchAttributeProgrammaticStreamSerialization;
    attrs[0].val.programmaticStreamSerializationAllowed = 1;
    cfg.attrs = attrs;
    cfg.numAttrs = 1;
    cudaLaunchKernelEx(&cfg, fused_kernel, out);
}